// round 16
// baseline (speedup 1.0000x reference)
#include <cuda_runtime.h>
#include <math.h>

#define B   10
#define V   50257
#define D   1024
#define T   20
#define NCHUNK 26
#define CHUNK  2048   // 26*2048 = 53248 >= V
#define TKBLOCKS (NCHUNK * B)

#define RNN_KS 32     // rnn k-slices of 32
#define NKS   9       // logits k-slices: 8x112 + 128 = 1024
#define KSL   112
#define NCB   50      // logits col-blocks (50*1024 = 51200 >= V)

// ------------------------- device scratch (no allocs allowed) -------------
__device__ float g_lpart[NKS][B * V];        // k-split partial logits
__device__ float g_pm[B * NCHUNK];
__device__ float g_ps[B * NCHUNK];
__device__ float g_pv[B * NCHUNK * B];
__device__ int   g_pi[B * NCHUNK * B];
__device__ int   g_tokens[B];
__device__ int   g_q[B];
__device__ int   g_seq[2][T * B];
__device__ float g_lp[2][T * B];
__device__ float g_bsum[2][B];
__device__ float g_h[2][B * D];
__device__ float g_rpart[RNN_KS][B * D];
__device__ __align__(16) unsigned long long g_hdup[D * B];  // (h,h) per k,b
__device__ int   g_tk_ctr;                   // zero-init; reset by last block

// --------------------------- helpers ---------------------------------------
__device__ __forceinline__ unsigned long long fma2(unsigned long long a,
                                                   unsigned long long b,
                                                   unsigned long long c) {
    unsigned long long d;
    asm("fma.rn.f32x2 %0, %1, %2, %3;" : "=l"(d) : "l"(a), "l"(b), "l"(c));
    return d;
}
__device__ __forceinline__ unsigned long long pack2(float w) {
    unsigned int wu = __float_as_uint(w);
    unsigned long long r;
    asm("mov.b64 %0, {%1, %1};" : "=l"(r) : "r"(wu));
    return r;
}
__device__ __forceinline__ unsigned long long packab(float a, float b) {
    unsigned long long r;
    asm("mov.b64 %0, {%1, %2};" : "=l"(r) : "r"(__float_as_uint(a)), "r"(__float_as_uint(b)));
    return r;
}
__device__ __forceinline__ void unpack2(unsigned long long a, float& lo, float& hi) {
    unsigned int l, h;
    asm("mov.b64 {%0, %1}, %2;" : "=r"(l), "=r"(h) : "l"(a));
    lo = __uint_as_float(l); hi = __uint_as_float(h);
}

// ===================== fused top-k + select =================================
// grid (NCHUNK, B) = 260 blocks, 256 threads. Phase 1: per-chunk top-10 +
// logsumexp partial (t>0 sums NKS partials). Phase 2: the last block to
// arrive performs the per-beam merge + global select + bookkeeping.
__global__ __launch_bounds__(256) void topksel_kernel(
        const float* __restrict__ src, int use_input, int t, int cur) {
    const int beam = blockIdx.y, chunk = blockIdx.x, tid = threadIdx.x;
    const int wid = tid >> 5, lane = tid & 31;
    const unsigned FULL = 0xffffffffu;
    const int rb = beam * V;
    const int c0 = chunk * CHUNK;
    const int c1 = min(c0 + CHUNK, V);

    // ---------------- phase 1 ----------------
    float m = -1e30f, s = 0.f;
    float tv[10]; int ti[10];
#pragma unroll
    for (int p = 0; p < 10; p++) { tv[p] = -1e30f; ti[p] = 0x7FFFFFFF; }

    for (int c = c0 + tid; c < c1; c += 256) {
        float x;
        if (use_input) x = src[rb + c];
        else {
            x = 0.f;
#pragma unroll
            for (int ks = 0; ks < NKS; ks++) x += g_lpart[ks][rb + c];
        }
        if (x > m) { s = s * __expf(m - x) + 1.f; m = x; }
        else       { s += __expf(x - m); }
        float v = (c == V - 1) ? x - 1000.f : x;    // UNK suppression (top-k only)
        if (v > tv[9] || (v == tv[9] && c < ti[9])) {
            tv[9] = v; ti[9] = c;
#pragma unroll
            for (int p = 9; p > 0; p--) {
                bool sw = (tv[p] > tv[p-1]) || (tv[p] == tv[p-1] && ti[p] < ti[p-1]);
                if (sw) {
                    float tf = tv[p]; tv[p] = tv[p-1]; tv[p-1] = tf;
                    int   tt = ti[p]; ti[p] = ti[p-1]; ti[p-1] = tt;
                }
            }
        }
    }

#pragma unroll
    for (int off = 16; off > 0; off >>= 1) {
        float m2 = __shfl_down_sync(FULL, m, off);
        float s2 = __shfl_down_sync(FULL, s, off);
        float mm = fmaxf(m, m2);
        s = s * __expf(m - mm) + s2 * __expf(m2 - mm);
        m = mm;
    }

    __shared__ float swv[8][10]; __shared__ int swi[8][10];
    __shared__ float swm[8], sws[8];
    if (lane == 0) { swm[wid] = m; sws[wid] = s; }

    for (int r = 0; r < 10; r++) {
        float v = tv[0]; int idx = ti[0];
#pragma unroll
        for (int off = 16; off > 0; off >>= 1) {
            float v2 = __shfl_down_sync(FULL, v, off);
            int   i2 = __shfl_down_sync(FULL, idx, off);
            if (v2 > v || (v2 == v && i2 < idx)) { v = v2; idx = i2; }
        }
        v = __shfl_sync(FULL, v, 0); idx = __shfl_sync(FULL, idx, 0);
        if (lane == 0) { swv[wid][r] = v; swi[wid][r] = idx; }
        if (ti[0] == idx) {
#pragma unroll
            for (int p = 0; p < 9; p++) { tv[p] = tv[p+1]; ti[p] = ti[p+1]; }
            tv[9] = -1e30f; ti[9] = 0x7FFFFFFF;
        }
    }
    __syncthreads();

    if (wid == 0) {
        float m8 = (lane < 8) ? swm[lane] : -1e30f;
        float s8 = (lane < 8) ? sws[lane] : 0.f;
#pragma unroll
        for (int off = 4; off > 0; off >>= 1) {
            float m2 = __shfl_down_sync(FULL, m8, off);
            float s2 = __shfl_down_sync(FULL, s8, off);
            float mm = fmaxf(m8, m2);
            s8 = s8 * __expf(m8 - mm) + s2 * __expf(m2 - mm);
            m8 = mm;
        }
        if (lane == 0) { g_pm[beam * NCHUNK + chunk] = m8; g_ps[beam * NCHUNK + chunk] = s8; }

        float lv[10]; int li[10];
        if (lane < 8) {
#pragma unroll
            for (int p = 0; p < 10; p++) { lv[p] = swv[lane][p]; li[p] = swi[lane][p]; }
        } else {
#pragma unroll
            for (int p = 0; p < 10; p++) { lv[p] = -1e30f; li[p] = 0x7FFFFFFF; }
        }
        for (int r = 0; r < 10; r++) {
            float v = lv[0]; int idx = li[0]; int l = lane;
#pragma unroll
            for (int off = 4; off > 0; off >>= 1) {
                float v2 = __shfl_down_sync(FULL, v, off);
                int   i2 = __shfl_down_sync(FULL, idx, off);
                int   l2 = __shfl_down_sync(FULL, l, off);
                if (v2 > v || (v2 == v && i2 < idx)) { v = v2; idx = i2; l = l2; }
            }
            v = __shfl_sync(FULL, v, 0); idx = __shfl_sync(FULL, idx, 0); l = __shfl_sync(FULL, l, 0);
            if (lane == 0) {
                int slot = (beam * NCHUNK + chunk) * 10 + r;
                g_pv[slot] = v; g_pi[slot] = idx;
            }
            if (lane == l) {
#pragma unroll
                for (int p = 0; p < 9; p++) { lv[p] = lv[p+1]; li[p] = li[p+1]; }
                lv[9] = -1e30f; li[9] = 0x7FFFFFFF;
            }
        }
    }

    // ---------------- phase 2: last block selects ----------------
    __shared__ int s_last;
    __threadfence();
    __syncthreads();
    if (tid == 0) {
        int old = atomicAdd(&g_tk_ctr, 1);
        s_last = (old == TKBLOCKS - 1) ? 1 : 0;
        if (s_last) g_tk_ctr = 0;
    }
    __syncthreads();
    if (!s_last) return;
    __threadfence();

    __shared__ float s_topv[100];
    __shared__ int   s_topi[100];
    __shared__ int   s_q[10], s_tok[10];
    __shared__ float s_loc[10], s_ns[10];
    int nxt = cur ^ 1;

    for (int bm = wid; bm < 10; bm += 8) {
        float mm2 = -1e30f, ss2 = 0.f;
        if (lane < NCHUNK) { mm2 = g_pm[bm * NCHUNK + lane]; ss2 = g_ps[bm * NCHUNK + lane]; }
#pragma unroll
        for (int off = 16; off > 0; off >>= 1) {
            float m2 = __shfl_down_sync(FULL, mm2, off);
            float s2 = __shfl_down_sync(FULL, ss2, off);
            float mx = fmaxf(mm2, m2);
            ss2 = ss2 * __expf(mm2 - mx) + s2 * __expf(m2 - mx);
            mm2 = mx;
        }
        float mf = __shfl_sync(FULL, mm2, 0);
        float sf = __shfl_sync(FULL, ss2, 0);
        float lse = logf(sf) + mf;

        float lv[10]; int li[10];
        if (lane < NCHUNK) {
            int base = (bm * NCHUNK + lane) * 10;
#pragma unroll
            for (int p = 0; p < 10; p++) { lv[p] = g_pv[base + p]; li[p] = g_pi[base + p]; }
        } else {
#pragma unroll
            for (int p = 0; p < 10; p++) { lv[p] = -1e30f; li[p] = 0x7FFFFFFF; }
        }
        for (int r = 0; r < 10; r++) {
            float v = lv[0]; int c = li[0]; int l = lane;
#pragma unroll
            for (int off = 16; off > 0; off >>= 1) {
                float v2 = __shfl_down_sync(FULL, v, off);
                int   c2 = __shfl_down_sync(FULL, c, off);
                int   l2 = __shfl_down_sync(FULL, l, off);
                if (v2 > v || (v2 == v && c2 < c)) { v = v2; c = c2; l = l2; }
            }
            v = __shfl_sync(FULL, v, 0); c = __shfl_sync(FULL, c, 0); l = __shfl_sync(FULL, l, 0);
            if (lane == 0) { s_topv[bm * 10 + r] = v - lse; s_topi[bm * 10 + r] = c; }
            if (lane == l) {
#pragma unroll
                for (int p = 0; p < 9; p++) { lv[p] = lv[p+1]; li[p] = li[p+1]; }
                lv[9] = -1e30f; li[9] = 0x7FFFFFFF;
            }
        }
    }
    __syncthreads();

    if (wid == 0) {
        float cv[4]; int cf[4];
#pragma unroll
        for (int j = 0; j < 4; j++) {
            int f = lane + 32 * j;
            if (f < 100) {
                int i = f / 10;
                float val;
                if (t == 0) val = (i > 0) ? -1e10f : s_topv[f];
                else        val = g_bsum[cur][i] + s_topv[f];
                cv[j] = val; cf[j] = f;
            } else { cv[j] = -1e30f; cf[j] = 0x7FFFFFFF; }
        }
        for (int r = 0; r < 10; r++) {
            float bv = -1e30f; int bf = 0x7FFFFFFF;
#pragma unroll
            for (int j = 0; j < 4; j++)
                if (cv[j] > bv || (cv[j] == bv && cf[j] < bf)) { bv = cv[j]; bf = cf[j]; }
#pragma unroll
            for (int off = 16; off > 0; off >>= 1) {
                float v2 = __shfl_down_sync(FULL, bv, off);
                int   f2 = __shfl_down_sync(FULL, bf, off);
                if (v2 > bv || (v2 == bv && f2 < bf)) { bv = v2; bf = f2; }
            }
            bv = __shfl_sync(FULL, bv, 0); bf = __shfl_sync(FULL, bf, 0);
            if (lane == 0) {
                int qq = bf / 10;
                s_q[r] = qq; s_tok[r] = s_topi[bf]; s_loc[r] = s_topv[bf]; s_ns[r] = bv;
            }
#pragma unroll
            for (int j = 0; j < 4; j++) if (cf[j] == bf) cv[j] = -1e30f;
        }
    }
    __syncthreads();

    if (tid < 10) {
        g_tokens[tid] = s_tok[tid];
        g_q[tid]      = s_q[tid];
        g_bsum[nxt][tid] = (s_tok[tid] == 0) ? -1000.0f : s_ns[tid];
    }
    for (int i = tid; i < T * B; i += 256) {
        int b = i % 10, row = i / 10;
        int sb = s_q[b];
        int sv; float lv2;
        if (row == t) { sv = s_tok[b]; lv2 = s_loc[b]; }
        else          { sv = g_seq[cur][row * 10 + sb]; lv2 = g_lp[cur][row * 10 + sb]; }
        g_seq[nxt][i] = sv; g_lp[nxt][i] = lv2;
    }
}

// --------------------------- RNN (split-K partials) ------------------------
// grid 128 = 4 col-blocks(256 cols) x 32 k-slices(32 k), 256 threads.
__global__ __launch_bounds__(256) void rnn_partial_kernel(
        const float* __restrict__ emb,
        const float* __restrict__ wx,
        const float* __restrict__ wh,
        const float* __restrict__ h0, int cur, int t) {
    __shared__ float se[32 * 12], shh[32 * 12];
    __shared__ int stok[10], sq[10];
    int bx = blockIdx.x;
    int cb = bx & 3, ks = bx >> 2;
    int tid = threadIdx.x;
    int k0 = ks * 32;
    int col = cb * 256 + tid;

    if (tid < 10) { stok[tid] = g_tokens[tid]; sq[tid] = g_q[tid]; }

    float wxv[32], whv[32];
#pragma unroll
    for (int kk = 0; kk < 32; kk++)
        wxv[kk] = __ldg(&wx[(size_t)(k0 + kk) * D + col]);
#pragma unroll
    for (int kk = 0; kk < 32; kk++)
        whv[kk] = __ldg(&wh[(size_t)(k0 + kk) * D + col]);

    const float* hsrc = (t == 0) ? h0 : g_h[cur];
    __syncthreads();
    for (int i = tid; i < 320; i += 256) {
        int b = i >> 5, kk = i & 31;
        se[kk * 12 + b]  = emb[(size_t)stok[b] * D + k0 + kk];
        shh[kk * 12 + b] = hsrc[sq[b] * D + k0 + kk];
    }
    __syncthreads();

    float acc[10];
#pragma unroll
    for (int b = 0; b < 10; b++) acc[b] = 0.f;
#pragma unroll
    for (int kk = 0; kk < 32; kk++) {
#pragma unroll
        for (int b = 0; b < 10; b++)
            acc[b] += se[kk * 12 + b] * wxv[kk] + shh[kk * 12 + b] * whv[kk];
    }
#pragma unroll
    for (int b = 0; b < 10; b++) g_rpart[ks][b * D + col] = acc[b];
}

// grid 160 x 64 (= exactly B*D threads). ALL 32 partial loads batched per
// thread: the entire 1.3MB input is in flight in one memory round trip.
__global__ __launch_bounds__(64) void rnn_combine_kernel(int nxt) {
    int i = blockIdx.x * 64 + threadIdx.x;
    float p[RNN_KS];
#pragma unroll
    for (int j = 0; j < RNN_KS; j++) p[j] = g_rpart[j][i];
    float v = 0.f;
#pragma unroll
    for (int j = 0; j < RNN_KS; j++) v += p[j];
    float hv = tanhf(v);
    g_h[nxt][i] = hv;
    int b = i >> 10, k = i & 1023;
    g_hdup[k * 10 + b] = pack2(hv);   // duplicated form for logits
}

// --------------------------- logits = h @ wo (column-packed f32x2) ---------
// grid (50 col-blocks, 9 k-slices) = 450 blocks -> 3/SM, 256 threads.
// Thread t owns 4 coalesced cols (c0, +256, +512, +768) as 2 f32x2 acc sets.
#define LOGT  256
#define LKB   4
__global__ __launch_bounds__(LOGT, 3) void logits_kernel(const float* __restrict__ wo) {
    __shared__ unsigned long long sh[128 * 10];
    const int cb = blockIdx.x, ks = blockIdx.y;
    const int k0 = ks * KSL;
    const int nk = (ks == NKS - 1) ? (D - (NKS - 1) * KSL) : KSL;  // 112 or 128

    for (int i = threadIdx.x; i < nk * 10; i += LOGT) sh[i] = g_hdup[k0 * 10 + i];
    __syncthreads();

    const int t = threadIdx.x;
    const int c0 = cb * 1024 + t;
    const int c1 = c0 + 256, c2 = c0 + 512, c3 = c0 + 768;
    if (c0 >= V) return;
    const bool ok1 = (c1 < V), ok2 = (c2 < V), ok3 = (c3 < V);

    const ulonglong2* sd2 = (const ulonglong2*)sh;

    unsigned long long accA[10], accB[10];
#pragma unroll
    for (int b = 0; b < 10; b++) { accA[b] = 0ull; accB[b] = 0ull; }

    for (int kk = 0; kk < nk; kk += LKB) {
        float w0[LKB], w1[LKB], w2[LKB], w3[LKB];
        const float* wb = wo + (size_t)(k0 + kk) * V;
#pragma unroll
        for (int i = 0; i < LKB; i++) w0[i] = __ldg(wb + (size_t)i * V + c0);
#pragma unroll
        for (int i = 0; i < LKB; i++) w1[i] = ok1 ? __ldg(wb + (size_t)i * V + c1) : 0.f;
#pragma unroll
        for (int i = 0; i < LKB; i++) w2[i] = ok2 ? __ldg(wb + (size_t)i * V + c2) : 0.f;
#pragma unroll
        for (int i = 0; i < LKB; i++) w3[i] = ok3 ? __ldg(wb + (size_t)i * V + c3) : 0.f;
#pragma unroll
        for (int i = 0; i < LKB; i++) {
            const int kl = kk + i;
            unsigned long long wA = packab(w0[i], w1[i]);
            unsigned long long wB = packab(w2[i], w3[i]);
            ulonglong2 pA = sd2[kl * 5 + 0];
            ulonglong2 pB = sd2[kl * 5 + 1];
            ulonglong2 pC = sd2[kl * 5 + 2];
            ulonglong2 pD = sd2[kl * 5 + 3];
            ulonglong2 pE = sd2[kl * 5 + 4];
            accA[0] = fma2(pA.x, wA, accA[0]);  accB[0] = fma2(pA.x, wB, accB[0]);
            accA[1] = fma2(pA.y, wA, accA[1]);  accB[1] = fma2(pA.y, wB, accB[1]);
            accA[2] = fma2(pB.x, wA, accA[2]);  accB[2] = fma2(pB.x, wB, accB[2]);
            accA[3] = fma2(pB.y, wA, accA[3]);  accB[3] = fma2(pB.y, wB, accB[3]);
            accA[4] = fma2(pC.x, wA, accA[4]);  accB[4] = fma2(pC.x, wB, accB[4]);
            accA[5] = fma2(pC.y, wA, accA[5]);  accB[5] = fma2(pC.y, wB, accB[5]);
            accA[6] = fma2(pD.x, wA, accA[6]);  accB[6] = fma2(pD.x, wB, accB[6]);
            accA[7] = fma2(pD.y, wA, accA[7]);  accB[7] = fma2(pD.y, wB, accB[7]);
            accA[8] = fma2(pE.x, wA, accA[8]);  accB[8] = fma2(pE.x, wB, accB[8]);
            accA[9] = fma2(pE.y, wA, accA[9]);  accB[9] = fma2(pE.y, wB, accB[9]);
        }
    }

    float* dst = g_lpart[ks];
#pragma unroll
    for (int b = 0; b < 10; b++) {
        float lo, hi;
        unpack2(accA[b], lo, hi);
        dst[b * V + c0] = lo;
        if (ok1) dst[b * V + c1] = hi;
        unpack2(accB[b], lo, hi);
        if (ok2) dst[b * V + c2] = lo;
        if (ok3) dst[b * V + c3] = hi;
    }
}

// --------------------------- finalize ---------------------------------------
__global__ void finalize_kernel(float* __restrict__ out, int cur) {
    int i = blockIdx.x * 256 + threadIdx.x;
    if (i < T * B)               out[i] = (float)g_seq[cur][i];
    else if (i < 2 * T * B)      out[i] = g_lp[cur][i - T * B];
    else if (i < 2 * T * B + B)  out[i] = g_bsum[cur][i - 2 * T * B];
}

// --------------------------- host driver ------------------------------------
extern "C" void kernel_launch(void* const* d_in, const int* in_sizes, int n_in,
                              void* d_out, int out_size) {
    const float* logprobs0 = (const float*)d_in[0];
    const float* h0        = (const float*)d_in[1];
    const float* emb       = (const float*)d_in[2];
    const float* wx        = (const float*)d_in[3];
    const float* wh        = (const float*)d_in[4];
    const float* wo        = (const float*)d_in[5];
    float* out = (float*)d_out;

    int cur = 0;
    for (int t = 0; t < T; t++) {
        dim3 gtp(NCHUNK, B);
        topksel_kernel<<<gtp, 256>>>(logprobs0, t == 0 ? 1 : 0, t, cur);
        if (t < T - 1) {
            rnn_partial_kernel<<<128, 256>>>(emb, wx, wh, h0, cur, t);
            rnn_combine_kernel<<<160, 64>>>(cur ^ 1);
            logits_kernel<<<dim3(NCB, NKS), LOGT>>>(wo);
        }
        cur ^= 1;
    }
    finalize_kernel<<<2, 256>>>(out, cur);
}

// round 17
// speedup vs baseline: 1.0310x; 1.0310x over previous
#include <cuda_runtime.h>
#include <math.h>

#define B   10
#define V   50257
#define V4  50260     // padded row length for g_lpart (float4-aligned)
#define D   1024
#define T   20
#define NCHUNK 26
#define CHUNK  2048   // 26*2048 = 53248 >= V
#define TKBLOCKS (NCHUNK * B)

#define RNN_KS 32     // rnn k-slices of 32
#define RNN_BLOCKS 128
#define NKS   9       // logits k-slices: 8x112 + 128 = 1024
#define KSL   112
#define NCB   33      // logits col-blocks (33*1536 = 50688 >= V)

// ------------------------- device scratch (no allocs allowed) -------------
__device__ __align__(16) float g_lpart[NKS][B * V4];  // padded partial logits
__device__ float g_pm[B * NCHUNK];
__device__ float g_ps[B * NCHUNK];
__device__ float g_pv[B * NCHUNK * B];
__device__ int   g_pi[B * NCHUNK * B];
__device__ int   g_tokens[B];
__device__ int   g_q[B];
__device__ int   g_seq[2][T * B];
__device__ float g_lp[2][T * B];
__device__ float g_bsum[2][B];
__device__ float g_h[2][B * D];
__device__ float g_rpart[RNN_KS][B * D];
__device__ __align__(16) unsigned long long g_hdup[D * B];  // (h,h) per k,b
__device__ int   g_tk_ctr;    // zero-init; reset by last topk block
__device__ int   g_rnn_ctr;   // zero-init; reset by topksel phase 2

// --------------------------- helpers ---------------------------------------
__device__ __forceinline__ unsigned long long fma2(unsigned long long a,
                                                   unsigned long long b,
                                                   unsigned long long c) {
    unsigned long long d;
    asm("fma.rn.f32x2 %0, %1, %2, %3;" : "=l"(d) : "l"(a), "l"(b), "l"(c));
    return d;
}
__device__ __forceinline__ unsigned long long pack2(float w) {
    unsigned int wu = __float_as_uint(w);
    unsigned long long r;
    asm("mov.b64 %0, {%1, %1};" : "=l"(r) : "r"(wu));
    return r;
}
__device__ __forceinline__ unsigned long long packab(float a, float b) {
    unsigned long long r;
    asm("mov.b64 %0, {%1, %2};" : "=l"(r) : "r"(__float_as_uint(a)), "r"(__float_as_uint(b)));
    return r;
}
__device__ __forceinline__ void unpack2(unsigned long long a, float& lo, float& hi) {
    unsigned int l, h;
    asm("mov.b64 {%0, %1}, %2;" : "=r"(l), "=r"(h) : "l"(a));
    lo = __uint_as_float(l); hi = __uint_as_float(h);
}

// ===================== fused top-k + select =================================
// grid (NCHUNK, B) = 260 blocks, 256 threads. Phase 1: per-chunk top-10 +
// logsumexp partial; for t>0 the NKS partials are summed via aligned float4
// loads (padded rows; pad lanes are never-written zeros, masked by c<V).
// Phase 2: last block merges + selects + resets g_rnn_ctr.
__global__ __launch_bounds__(256) void topksel_kernel(
        const float* __restrict__ src, int use_input, int t, int cur) {
    const int beam = blockIdx.y, chunk = blockIdx.x, tid = threadIdx.x;
    const int wid = tid >> 5, lane = tid & 31;
    const unsigned FULL = 0xffffffffu;
    const int c0 = chunk * CHUNK;
    const int c1 = min(c0 + CHUNK, V);

    // ---------------- phase 1 ----------------
    float m = -1e30f, s = 0.f;
    float tv[10]; int ti[10];
#pragma unroll
    for (int p = 0; p < 10; p++) { tv[p] = -1e30f; ti[p] = 0x7FFFFFFF; }

    if (use_input) {
        const int rb = beam * V;
        for (int c = c0 + tid; c < c1; c += 256) {
            float x = src[rb + c];
            if (x > m) { s = s * __expf(m - x) + 1.f; m = x; }
            else       { s += __expf(x - m); }
            float v = (c == V - 1) ? x - 1000.f : x;
            if (v > tv[9] || (v == tv[9] && c < ti[9])) {
                tv[9] = v; ti[9] = c;
#pragma unroll
                for (int p = 9; p > 0; p--) {
                    bool sw = (tv[p] > tv[p-1]) || (tv[p] == tv[p-1] && ti[p] < ti[p-1]);
                    if (sw) {
                        float tf = tv[p]; tv[p] = tv[p-1]; tv[p-1] = tf;
                        int   tt = ti[p]; ti[p] = ti[p-1]; ti[p-1] = tt;
                    }
                }
            }
        }
    } else {
        const int rb4 = beam * V4;
        for (int cc = c0 + (tid << 2); cc < c1; cc += 1024) {
            float4 x4 = *(const float4*)&g_lpart[0][rb4 + cc];
#pragma unroll
            for (int ks = 1; ks < NKS; ks++) {
                const float4 p = *(const float4*)&g_lpart[ks][rb4 + cc];
                x4.x += p.x; x4.y += p.y; x4.z += p.z; x4.w += p.w;
            }
            float xs[4] = {x4.x, x4.y, x4.z, x4.w};
#pragma unroll
            for (int j = 0; j < 4; j++) {
                int c = cc + j;
                if (c >= V) break;
                float x = xs[j];
                if (x > m) { s = s * __expf(m - x) + 1.f; m = x; }
                else       { s += __expf(x - m); }
                float v = (c == V - 1) ? x - 1000.f : x;
                if (v > tv[9] || (v == tv[9] && c < ti[9])) {
                    tv[9] = v; ti[9] = c;
#pragma unroll
                    for (int p = 9; p > 0; p--) {
                        bool sw = (tv[p] > tv[p-1]) || (tv[p] == tv[p-1] && ti[p] < ti[p-1]);
                        if (sw) {
                            float tf = tv[p]; tv[p] = tv[p-1]; tv[p-1] = tf;
                            int   tt = ti[p]; ti[p] = ti[p-1]; ti[p-1] = tt;
                        }
                    }
                }
            }
        }
    }

#pragma unroll
    for (int off = 16; off > 0; off >>= 1) {
        float m2 = __shfl_down_sync(FULL, m, off);
        float s2 = __shfl_down_sync(FULL, s, off);
        float mm = fmaxf(m, m2);
        s = s * __expf(m - mm) + s2 * __expf(m2 - mm);
        m = mm;
    }

    __shared__ float swv[8][10]; __shared__ int swi[8][10];
    __shared__ float swm[8], sws[8];
    if (lane == 0) { swm[wid] = m; sws[wid] = s; }

    for (int r = 0; r < 10; r++) {
        float v = tv[0]; int idx = ti[0];
#pragma unroll
        for (int off = 16; off > 0; off >>= 1) {
            float v2 = __shfl_down_sync(FULL, v, off);
            int   i2 = __shfl_down_sync(FULL, idx, off);
            if (v2 > v || (v2 == v && i2 < idx)) { v = v2; idx = i2; }
        }
        v = __shfl_sync(FULL, v, 0); idx = __shfl_sync(FULL, idx, 0);
        if (lane == 0) { swv[wid][r] = v; swi[wid][r] = idx; }
        if (ti[0] == idx) {
#pragma unroll
            for (int p = 0; p < 9; p++) { tv[p] = tv[p+1]; ti[p] = ti[p+1]; }
            tv[9] = -1e30f; ti[9] = 0x7FFFFFFF;
        }
    }
    __syncthreads();

    if (wid == 0) {
        float m8 = (lane < 8) ? swm[lane] : -1e30f;
        float s8 = (lane < 8) ? sws[lane] : 0.f;
#pragma unroll
        for (int off = 4; off > 0; off >>= 1) {
            float m2 = __shfl_down_sync(FULL, m8, off);
            float s2 = __shfl_down_sync(FULL, s8, off);
            float mm = fmaxf(m8, m2);
            s8 = s8 * __expf(m8 - mm) + s2 * __expf(m2 - mm);
            m8 = mm;
        }
        if (lane == 0) { g_pm[beam * NCHUNK + chunk] = m8; g_ps[beam * NCHUNK + chunk] = s8; }

        float lv[10]; int li[10];
        if (lane < 8) {
#pragma unroll
            for (int p = 0; p < 10; p++) { lv[p] = swv[lane][p]; li[p] = swi[lane][p]; }
        } else {
#pragma unroll
            for (int p = 0; p < 10; p++) { lv[p] = -1e30f; li[p] = 0x7FFFFFFF; }
        }
        for (int r = 0; r < 10; r++) {
            float v = lv[0]; int idx = li[0]; int l = lane;
#pragma unroll
            for (int off = 4; off > 0; off >>= 1) {
                float v2 = __shfl_down_sync(FULL, v, off);
                int   i2 = __shfl_down_sync(FULL, idx, off);
                int   l2 = __shfl_down_sync(FULL, l, off);
                if (v2 > v || (v2 == v && i2 < idx)) { v = v2; idx = i2; l = l2; }
            }
            v = __shfl_sync(FULL, v, 0); idx = __shfl_sync(FULL, idx, 0); l = __shfl_sync(FULL, l, 0);
            if (lane == 0) {
                int slot = (beam * NCHUNK + chunk) * 10 + r;
                g_pv[slot] = v; g_pi[slot] = idx;
            }
            if (lane == l) {
#pragma unroll
                for (int p = 0; p < 9; p++) { lv[p] = lv[p+1]; li[p] = li[p+1]; }
                lv[9] = -1e30f; li[9] = 0x7FFFFFFF;
            }
        }
    }

    // ---------------- phase 2: last block selects ----------------
    __shared__ int s_last;
    __threadfence();
    __syncthreads();
    if (tid == 0) {
        int old = atomicAdd(&g_tk_ctr, 1);
        s_last = (old == TKBLOCKS - 1) ? 1 : 0;
        if (s_last) { g_tk_ctr = 0; g_rnn_ctr = 0; }
    }
    __syncthreads();
    if (!s_last) return;
    __threadfence();

    __shared__ float s_topv[100];
    __shared__ int   s_topi[100];
    __shared__ int   s_q[10], s_tok[10];
    __shared__ float s_loc[10], s_ns[10];
    int nxt = cur ^ 1;

    for (int bm = wid; bm < 10; bm += 8) {
        float mm2 = -1e30f, ss2 = 0.f;
        if (lane < NCHUNK) { mm2 = g_pm[bm * NCHUNK + lane]; ss2 = g_ps[bm * NCHUNK + lane]; }
#pragma unroll
        for (int off = 16; off > 0; off >>= 1) {
            float m2 = __shfl_down_sync(FULL, mm2, off);
            float s2 = __shfl_down_sync(FULL, ss2, off);
            float mx = fmaxf(mm2, m2);
            ss2 = ss2 * __expf(mm2 - mx) + s2 * __expf(m2 - mx);
            mm2 = mx;
        }
        float mf = __shfl_sync(FULL, mm2, 0);
        float sf = __shfl_sync(FULL, ss2, 0);
        float lse = logf(sf) + mf;

        float lv[10]; int li[10];
        if (lane < NCHUNK) {
            int base = (bm * NCHUNK + lane) * 10;
#pragma unroll
            for (int p = 0; p < 10; p++) { lv[p] = g_pv[base + p]; li[p] = g_pi[base + p]; }
        } else {
#pragma unroll
            for (int p = 0; p < 10; p++) { lv[p] = -1e30f; li[p] = 0x7FFFFFFF; }
        }
        for (int r = 0; r < 10; r++) {
            float v = lv[0]; int c = li[0]; int l = lane;
#pragma unroll
            for (int off = 16; off > 0; off >>= 1) {
                float v2 = __shfl_down_sync(FULL, v, off);
                int   c2 = __shfl_down_sync(FULL, c, off);
                int   l2 = __shfl_down_sync(FULL, l, off);
                if (v2 > v || (v2 == v && c2 < c)) { v = v2; c = c2; l = l2; }
            }
            v = __shfl_sync(FULL, v, 0); c = __shfl_sync(FULL, c, 0); l = __shfl_sync(FULL, l, 0);
            if (lane == 0) { s_topv[bm * 10 + r] = v - lse; s_topi[bm * 10 + r] = c; }
            if (lane == l) {
#pragma unroll
                for (int p = 0; p < 9; p++) { lv[p] = lv[p+1]; li[p] = li[p+1]; }
                lv[9] = -1e30f; li[9] = 0x7FFFFFFF;
            }
        }
    }
    __syncthreads();

    if (wid == 0) {
        float cv[4]; int cf[4];
#pragma unroll
        for (int j = 0; j < 4; j++) {
            int f = lane + 32 * j;
            if (f < 100) {
                int i = f / 10;
                float val;
                if (t == 0) val = (i > 0) ? -1e10f : s_topv[f];
                else        val = g_bsum[cur][i] + s_topv[f];
                cv[j] = val; cf[j] = f;
            } else { cv[j] = -1e30f; cf[j] = 0x7FFFFFFF; }
        }
        for (int r = 0; r < 10; r++) {
            float bv = -1e30f; int bf = 0x7FFFFFFF;
#pragma unroll
            for (int j = 0; j < 4; j++)
                if (cv[j] > bv || (cv[j] == bv && cf[j] < bf)) { bv = cv[j]; bf = cf[j]; }
#pragma unroll
            for (int off = 16; off > 0; off >>= 1) {
                float v2 = __shfl_down_sync(FULL, bv, off);
                int   f2 = __shfl_down_sync(FULL, bf, off);
                if (v2 > bv || (v2 == bv && f2 < bf)) { bv = v2; bf = f2; }
            }
            bv = __shfl_sync(FULL, bv, 0); bf = __shfl_sync(FULL, bf, 0);
            if (lane == 0) {
                int qq = bf / 10;
                s_q[r] = qq; s_tok[r] = s_topi[bf]; s_loc[r] = s_topv[bf]; s_ns[r] = bv;
            }
#pragma unroll
            for (int j = 0; j < 4; j++) if (cf[j] == bf) cv[j] = -1e30f;
        }
    }
    __syncthreads();

    if (tid < 10) {
        g_tokens[tid] = s_tok[tid];
        g_q[tid]      = s_q[tid];
        g_bsum[nxt][tid] = (s_tok[tid] == 0) ? -1000.0f : s_ns[tid];
    }
    for (int i = tid; i < T * B; i += 256) {
        int b = i % 10, row = i / 10;
        int sb = s_q[b];
        int sv; float lv2;
        if (row == t) { sv = s_tok[b]; lv2 = s_loc[b]; }
        else          { sv = g_seq[cur][row * 10 + sb]; lv2 = g_lp[cur][row * 10 + sb]; }
        g_seq[nxt][i] = sv; g_lp[nxt][i] = lv2;
    }
}

// ========== fused RNN: split-K partials + grid-sync + distributed combine ==
// grid 128 = 4 col-blocks(256 cols) x 32 k-slices(32 k), 256 threads.
// All 128 blocks are co-resident (<=148 SMs) -> spin on g_rnn_ctr is safe.
// g_rnn_ctr is reset by topksel phase 2 between launches.
__global__ __launch_bounds__(256) void rnn_kernel(
        const float* __restrict__ emb,
        const float* __restrict__ wx,
        const float* __restrict__ wh,
        const float* __restrict__ h0, int cur, int t) {
    __shared__ float se[32 * 12], shh[32 * 12];
    __shared__ int stok[10], sq[10];
    int bx = blockIdx.x;
    int cb = bx & 3, ks = bx >> 2;
    int tid = threadIdx.x;
    int k0 = ks * 32;
    int col = cb * 256 + tid;

    if (tid < 10) { stok[tid] = g_tokens[tid]; sq[tid] = g_q[tid]; }

    float wxv[32], whv[32];
#pragma unroll
    for (int kk = 0; kk < 32; kk++)
        wxv[kk] = __ldg(&wx[(size_t)(k0 + kk) * D + col]);
#pragma unroll
    for (int kk = 0; kk < 32; kk++)
        whv[kk] = __ldg(&wh[(size_t)(k0 + kk) * D + col]);

    const float* hsrc = (t == 0) ? h0 : g_h[cur];
    __syncthreads();
    for (int i = tid; i < 320; i += 256) {
        int b = i >> 5, kk = i & 31;
        se[kk * 12 + b]  = emb[(size_t)stok[b] * D + k0 + kk];
        shh[kk * 12 + b] = hsrc[sq[b] * D + k0 + kk];
    }
    __syncthreads();

    float acc[10];
#pragma unroll
    for (int b = 0; b < 10; b++) acc[b] = 0.f;
#pragma unroll
    for (int kk = 0; kk < 32; kk++) {
#pragma unroll
        for (int b = 0; b < 10; b++)
            acc[b] += se[kk * 12 + b] * wxv[kk] + shh[kk * 12 + b] * whv[kk];
    }
#pragma unroll
    for (int b = 0; b < 10; b++) g_rpart[ks][b * D + col] = acc[b];

    // ----- grid-wide sync (all blocks resident) -----
    __threadfence();
    __syncthreads();
    if (tid == 0) {
        atomicAdd(&g_rnn_ctr, 1);
        volatile int* ctr = &g_rnn_ctr;
        while (*ctr < RNN_BLOCKS) { }
    }
    __syncthreads();
    __threadfence();

    // ----- distributed combine: 32768 threads, first 10240 active -----
    int gid = bx * 256 + tid;
    if (gid < B * D) {
        float p[RNN_KS];
#pragma unroll
        for (int j = 0; j < RNN_KS; j++) p[j] = g_rpart[j][gid];
        float v = 0.f;
#pragma unroll
        for (int j = 0; j < RNN_KS; j++) v += p[j];
        float hv = tanhf(v);
        g_h[cur ^ 1][gid] = hv;
        int b = gid >> 10, k = gid & 1023;
        g_hdup[k * 10 + b] = pack2(hv);
    }
}

// --------------------------- logits = h @ wo (column-packed f32x2) ---------
// grid (33 col-blocks, 9 k-slices) = 297 blocks -> 2/SM, 384 threads.
// Thread t owns 4 coalesced cols (c0, +384, +768, +1152) as 2 f32x2 acc sets.
// Stores into the PADDED g_lpart rows (stride V4).
#define LOGT  384
#define LKB   4
__global__ __launch_bounds__(LOGT, 2) void logits_kernel(const float* __restrict__ wo) {
    __shared__ unsigned long long sh[128 * 10];
    const int cb = blockIdx.x, ks = blockIdx.y;
    const int k0 = ks * KSL;
    const int nk = (ks == NKS - 1) ? (D - (NKS - 1) * KSL) : KSL;  // 112 or 128

    for (int i = threadIdx.x; i < nk * 10; i += LOGT) sh[i] = g_hdup[k0 * 10 + i];
    __syncthreads();

    const int t = threadIdx.x;
    const int c0 = cb * 1536 + t;
    const int c1 = c0 + 384, c2 = c0 + 768, c3 = c0 + 1152;
    if (c0 >= V) return;
    const bool ok1 = (c1 < V), ok2 = (c2 < V), ok3 = (c3 < V);

    const ulonglong2* sd2 = (const ulonglong2*)sh;

    unsigned long long accA[10], accB[10];
#pragma unroll
    for (int b = 0; b < 10; b++) { accA[b] = 0ull; accB[b] = 0ull; }

    for (int kk = 0; kk < nk; kk += LKB) {
        float w0[LKB], w1[LKB], w2[LKB], w3[LKB];
        const float* wb = wo + (size_t)(k0 + kk) * V;
#pragma unroll
        for (int i = 0; i < LKB; i++) w0[i] = __ldg(wb + (size_t)i * V + c0);
#pragma unroll
        for (int i = 0; i < LKB; i++) w1[i] = ok1 ? __ldg(wb + (size_t)i * V + c1) : 0.f;
#pragma unroll
        for (int i = 0; i < LKB; i++) w2[i] = ok2 ? __ldg(wb + (size_t)i * V + c2) : 0.f;
#pragma unroll
        for (int i = 0; i < LKB; i++) w3[i] = ok3 ? __ldg(wb + (size_t)i * V + c3) : 0.f;
#pragma unroll
        for (int i = 0; i < LKB; i++) {
            const int kl = kk + i;
            unsigned long long wA = packab(w0[i], w1[i]);
            unsigned long long wB = packab(w2[i], w3[i]);
            ulonglong2 pA = sd2[kl * 5 + 0];
            ulonglong2 pB = sd2[kl * 5 + 1];
            ulonglong2 pC = sd2[kl * 5 + 2];
            ulonglong2 pD = sd2[kl * 5 + 3];
            ulonglong2 pE = sd2[kl * 5 + 4];
            accA[0] = fma2(pA.x, wA, accA[0]);  accB[0] = fma2(pA.x, wB, accB[0]);
            accA[1] = fma2(pA.y, wA, accA[1]);  accB[1] = fma2(pA.y, wB, accB[1]);
            accA[2] = fma2(pB.x, wA, accA[2]);  accB[2] = fma2(pB.x, wB, accB[2]);
            accA[3] = fma2(pB.y, wA, accA[3]);  accB[3] = fma2(pB.y, wB, accB[3]);
            accA[4] = fma2(pC.x, wA, accA[4]);  accB[4] = fma2(pC.x, wB, accB[4]);
            accA[5] = fma2(pC.y, wA, accA[5]);  accB[5] = fma2(pC.y, wB, accB[5]);
            accA[6] = fma2(pD.x, wA, accA[6]);  accB[6] = fma2(pD.x, wB, accB[6]);
            accA[7] = fma2(pD.y, wA, accA[7]);  accB[7] = fma2(pD.y, wB, accB[7]);
            accA[8] = fma2(pE.x, wA, accA[8]);  accB[8] = fma2(pE.x, wB, accB[8]);
            accA[9] = fma2(pE.y, wA, accA[9]);  accB[9] = fma2(pE.y, wB, accB[9]);
        }
    }

    float* dst = g_lpart[ks];
#pragma unroll
    for (int b = 0; b < 10; b++) {
        float lo, hi;
        unpack2(accA[b], lo, hi);
        dst[b * V4 + c0] = lo;
        if (ok1) dst[b * V4 + c1] = hi;
        unpack2(accB[b], lo, hi);
        if (ok2) dst[b * V4 + c2] = lo;
        if (ok3) dst[b * V4 + c3] = hi;
    }
}

// --------------------------- finalize ---------------------------------------
__global__ void finalize_kernel(float* __restrict__ out, int cur) {
    int i = blockIdx.x * 256 + threadIdx.x;
    if (i < T * B)               out[i] = (float)g_seq[cur][i];
    else if (i < 2 * T * B)      out[i] = g_lp[cur][i - T * B];
    else if (i < 2 * T * B + B)  out[i] = g_bsum[cur][i - 2 * T * B];
}

// --------------------------- host driver ------------------------------------
extern "C" void kernel_launch(void* const* d_in, const int* in_sizes, int n_in,
                              void* d_out, int out_size) {
    const float* logprobs0 = (const float*)d_in[0];
    const float* h0        = (const float*)d_in[1];
    const float* emb       = (const float*)d_in[2];
    const float* wx        = (const float*)d_in[3];
    const float* wh        = (const float*)d_in[4];
    const float* wo        = (const float*)d_in[5];
    float* out = (float*)d_out;

    int cur = 0;
    for (int t = 0; t < T; t++) {
        dim3 gtp(NCHUNK, B);
        topksel_kernel<<<gtp, 256>>>(logprobs0, t == 0 ? 1 : 0, t, cur);
        if (t < T - 1) {
            rnn_kernel<<<RNN_BLOCKS, 256>>>(emb, wx, wh, h0, cur, t);
            logits_kernel<<<dim3(NCB, NKS), LOGT>>>(wo);
        }
        cur ^= 1;
    }
    finalize_kernel<<<2, 256>>>(out, cur);
}